// round 8
// baseline (speedup 1.0000x reference)
#include <cuda_runtime.h>
#include <cstdint>

// SlidingWindowAttentionNoOverlap: B=4,S=8192,H=16,D=64,w=128.
// mma.sync bf16-split path (base compute_103 PTX; no tcgen05).
// CTA = (b,h,chunk,half): 64 queries. 12 warps = 4 rowgroups(16q) x 3 chunk-cols(128).
// d_out layout: [out: B*S*H*64 f32][attn: B*S*H*384 f32].

constexpr int Bn = 4, Sn = 8192, Hn = 16, Dn = 64, Wn = 128, Cn = 64;
constexpr int NT = 384;

constexpr int QSTR = 144;               // Q/K smem row stride (bytes)
constexpr int VSTR = 784;               // V^T smem row stride (bytes)
constexpr int SM_Q  = 0;                // Q hi 64x144, lo at +9216
constexpr int SM_QL = 9216;
constexpr int SM_K  = 18432;            // K hi 384x144, lo at +55296
constexpr int SM_KL = 55296;
constexpr int SM_VT = 129024;           // V^T hi 64x784, lo at +50176
constexpr int SM_VL = 50176;
constexpr int SMEM_TOTAL = 229376;
constexpr int SCRMS = 16384;            // softmax scratch (bytes, inside dead Q area)
constexpr int OSTR = 66;                // out-reduce scratch stride (floats)

__device__ __forceinline__ uint32_t s2u(const void* p) {
    uint32_t a;
    asm("{ .reg .u64 t; cvta.to.shared.u64 t, %1; cvt.u32.u64 %0, t; }" : "=r"(a) : "l"(p));
    return a;
}
// pack (lo=a, hi=b) to bf16x2 + residual pack
__device__ __forceinline__ void split2(float a, float b, uint32_t& hp, uint32_t& lp) {
    uint32_t h;
    asm("cvt.rn.bf16x2.f32 %0, %1, %2;" : "=r"(h) : "f"(b), "f"(a));
    float ha = __uint_as_float(h << 16);
    float hb = __uint_as_float(h & 0xffff0000u);
    uint32_t l;
    asm("cvt.rn.bf16x2.f32 %0, %1, %2;" : "=r"(l) : "f"(b - hb), "f"(a - ha));
    hp = h; lp = l;
}
__device__ __forceinline__ void ldsm4(uint32_t r[4], uint32_t a) {
    asm volatile("ldmatrix.sync.aligned.m8n8.x4.shared.b16 {%0,%1,%2,%3}, [%4];"
        : "=r"(r[0]), "=r"(r[1]), "=r"(r[2]), "=r"(r[3]) : "r"(a));
}
__device__ __forceinline__ void mma16816(float c[4], uint32_t a0, uint32_t a1, uint32_t a2,
                                         uint32_t a3, uint32_t b0, uint32_t b1) {
    asm volatile("mma.sync.aligned.m16n8k16.row.col.f32.bf16.bf16.f32 "
        "{%0,%1,%2,%3}, {%4,%5,%6,%7}, {%8,%9}, {%0,%1,%2,%3};"
        : "+f"(c[0]), "+f"(c[1]), "+f"(c[2]), "+f"(c[3])
        : "r"(a0), "r"(a1), "r"(a2), "r"(a3), "r"(b0), "r"(b1));
}

__global__ void __launch_bounds__(NT, 1)
swa_mma(const float* __restrict__ gQ, const float* __restrict__ gK,
        const float* __restrict__ gV, float* __restrict__ gOut,
        float* __restrict__ gAttn)
{
    extern __shared__ char smem[];
    const uint32_t sb = s2u(smem);

    const int qh = blockIdx.x & 1, c = blockIdx.x >> 1;
    const int h = blockIdx.y, b = blockIdx.z;
    const int tid = threadIdx.x, lane = tid & 31, warp = tid >> 5;
    const int rg = warp & 3, e = warp >> 2;          // rowgroup 0..3, chunk col 0..2
    const int s0 = c * Wn + qh * 64;
    const int rowBase = (b * Sn + s0) * Hn + h;
    const bool e0 = (c > 0), e2 = (c < Cn - 1);
    const bool myok = (e == 0) ? e0 : (e == 2) ? e2 : true;   // warp-uniform

    // ================= stage Q (64x64), K (3x128x64), V^T (64x384) as bf16 hi/lo ======
    for (int i = tid; i < 1024; i += NT) {               // Q
        int r = i >> 4, dq = (i & 15) * 4;
        float4 v = *reinterpret_cast<const float4*>(gQ + (size_t)(rowBase + r * Hn) * Dn + dq);
        uint32_t h0, l0, h1, l1;
        split2(v.x, v.y, h0, l0); split2(v.z, v.w, h1, l1);
        *reinterpret_cast<uint2*>(smem + SM_Q + r * QSTR + dq * 2) = make_uint2(h0, h1);
        *reinterpret_cast<uint2*>(smem + SM_Q + SM_QL + r * QSTR + dq * 2) = make_uint2(l0, l1);
    }
    #pragma unroll
    for (int ec = 0; ec < 3; ec++) {
        const bool ok = (ec == 0) ? e0 : (ec == 2) ? e2 : true;
        if (!ok) continue;
        const int kr0 = (b * Sn + (c - 1 + ec) * Wn) * Hn + h;
        for (int i = tid; i < 2048; i += NT) {           // K chunk ec
            int r = i >> 4, dq = (i & 15) * 4;
            float4 v = *reinterpret_cast<const float4*>(gK + (size_t)(kr0 + r * Hn) * Dn + dq);
            uint32_t h0, l0, h1, l1;
            split2(v.x, v.y, h0, l0); split2(v.z, v.w, h1, l1);
            char* kb = smem + SM_K + (128 * ec + r) * QSTR + dq * 2;
            *reinterpret_cast<uint2*>(kb) = make_uint2(h0, h1);
            *reinterpret_cast<uint2*>(kb + SM_KL) = make_uint2(l0, l1);
        }
        for (int i = tid; i < 1024; i += NT) {           // V chunk ec -> V^T
            int y2 = i & 63, d4 = i >> 6;
            int y = 2 * y2, d = 4 * d4;
            const float* vp = gV + (size_t)(kr0 + y * Hn) * Dn + d;
            float4 va = *reinterpret_cast<const float4*>(vp);
            float4 vb = *reinterpret_cast<const float4*>(vp + (size_t)Hn * Dn);
            float ax[4] = {va.x, va.y, va.z, va.w};
            float bx[4] = {vb.x, vb.y, vb.z, vb.w};
            #pragma unroll
            for (int m = 0; m < 4; m++) {
                uint32_t hp, lp;
                split2(ax[m], bx[m], hp, lp);            // (y even -> lo, y odd -> hi)
                char* vt = smem + SM_VT + (d + m) * VSTR + (128 * ec + y) * 2;
                *reinterpret_cast<uint32_t*>(vt) = hp;
                *reinterpret_cast<uint32_t*>(vt + SM_VL) = lp;
            }
        }
    }
    __syncthreads();

    // ================= QK: S[16,128] per warp (chunk e), 3 split terms ================
    float s[16][4];
    #pragma unroll
    for (int j = 0; j < 16; j++)
        #pragma unroll
        for (int k = 0; k < 4; k++) s[j][k] = 0.0f;

    const uint32_t aQrow = (uint32_t)((16 * rg + (lane & 15)) * QSTR + (lane >> 4) * 16);
    const uint32_t bKrow = (uint32_t)((e * 128 + (lane & 7) + 8 * (lane >> 4)) * QSTR
                                      + ((lane >> 3) & 1) * 16);
    if (myok) {
        #pragma unroll
        for (int kk = 0; kk < 4; kk++) {
            uint32_t ah[4], al[4];
            ldsm4(ah, sb + SM_Q + aQrow + kk * 32);
            ldsm4(al, sb + SM_Q + SM_QL + aQrow + kk * 32);
            #pragma unroll
            for (int jp = 0; jp < 8; jp++) {
                const uint32_t ka = sb + SM_K + bKrow + jp * (16 * QSTR) + kk * 32;
                uint32_t bh[4], bl[4];
                ldsm4(bh, ka);
                mma16816(s[2 * jp],     ah[0], ah[1], ah[2], ah[3], bh[0], bh[1]);
                mma16816(s[2 * jp + 1], ah[0], ah[1], ah[2], ah[3], bh[2], bh[3]);
                mma16816(s[2 * jp],     al[0], al[1], al[2], al[3], bh[0], bh[1]);
                mma16816(s[2 * jp + 1], al[0], al[1], al[2], al[3], bh[2], bh[3]);
                ldsm4(bl, ka + SM_KL);
                mma16816(s[2 * jp],     ah[0], ah[1], ah[2], ah[3], bl[0], bl[1]);
                mma16816(s[2 * jp + 1], ah[0], ah[1], ah[2], ah[3], bl[2], bl[3]);
            }
        }
    }
    __syncthreads();    // all ldsm done; Q area -> softmax scratch, K area -> out scratch

    // ================= softmax over 384 (each row split across 3 chunk warps) =========
    float* scr = reinterpret_cast<float*>(smem + SCRMS);   // mx[3][64], sum[3][64]
    const int lr0 = 16 * rg + (lane >> 2);                 // local row via c0/c1; +8 via c2/c3

    float mx0 = -1e30f, mx1 = -1e30f;
    #pragma unroll
    for (int j = 0; j < 16; j++) {
        mx0 = fmaxf(mx0, fmaxf(s[j][0], s[j][1]));
        mx1 = fmaxf(mx1, fmaxf(s[j][2], s[j][3]));
    }
    mx0 = fmaxf(mx0, __shfl_xor_sync(~0u, mx0, 1)); mx0 = fmaxf(mx0, __shfl_xor_sync(~0u, mx0, 2));
    mx1 = fmaxf(mx1, __shfl_xor_sync(~0u, mx1, 1)); mx1 = fmaxf(mx1, __shfl_xor_sync(~0u, mx1, 2));
    if ((lane & 3) == 0) { scr[e * 64 + lr0] = mx0; scr[e * 64 + lr0 + 8] = mx1; }
    __syncthreads();
    const float mA = fmaxf(scr[lr0], fmaxf(scr[64 + lr0], scr[128 + lr0]));
    const float mB = fmaxf(scr[lr0 + 8], fmaxf(scr[64 + lr0 + 8], scr[128 + lr0 + 8]));

    float sm0 = 0.0f, sm1 = 0.0f;
    #pragma unroll
    for (int j = 0; j < 16; j++) {
        s[j][0] = __expf(s[j][0] - mA); s[j][1] = __expf(s[j][1] - mA);
        s[j][2] = __expf(s[j][2] - mB); s[j][3] = __expf(s[j][3] - mB);
        sm0 += s[j][0] + s[j][1];
        sm1 += s[j][2] + s[j][3];
    }
    sm0 += __shfl_xor_sync(~0u, sm0, 1); sm0 += __shfl_xor_sync(~0u, sm0, 2);
    sm1 += __shfl_xor_sync(~0u, sm1, 1); sm1 += __shfl_xor_sync(~0u, sm1, 2);
    if ((lane & 3) == 0) { scr[192 + e * 64 + lr0] = sm0; scr[192 + e * 64 + lr0 + 8] = sm1; }
    __syncthreads();
    const float inv0 = __frcp_rn(scr[192 + lr0] + scr[256 + lr0] + scr[320 + lr0]);
    const float inv1 = __frcp_rn(scr[192 + lr0 + 8] + scr[256 + lr0 + 8] + scr[320 + lr0 + 8]);

    // ---- normalize, write attn, repack C-frags -> bf16 A-frags (hi/lo) ----
    uint32_t hi01[16], hi23[16], lo01[16], lo23[16];
    {
        float* a0p = gAttn + (size_t)(rowBase + lr0 * Hn) * 384 + e * 128 + 2 * (lane & 3);
        float* a1p = a0p + (size_t)8 * Hn * 384;
        #pragma unroll
        for (int j = 0; j < 16; j++) {
            float p0 = s[j][0] * inv0, p1 = s[j][1] * inv0;
            float p2 = s[j][2] * inv1, p3 = s[j][3] * inv1;
            *reinterpret_cast<float2*>(a0p + 8 * j) = make_float2(p0, p1);
            *reinterpret_cast<float2*>(a1p + 8 * j) = make_float2(p2, p3);
            split2(p0, p1, hi01[j], lo01[j]);
            split2(p2, p3, hi23[j], lo23[j]);
        }
    }

    // ================= PV: O[16,64] partial over this warp's 128 y ====================
    float o[8][4];
    #pragma unroll
    for (int n = 0; n < 8; n++)
        #pragma unroll
        for (int k = 0; k < 4; k++) o[n][k] = 0.0f;

    const uint32_t bVrow = (uint32_t)(((lane & 7) + 8 * (lane >> 4)) * VSTR
                                      + ((lane >> 3) & 1) * 16);
    if (myok) {
        #pragma unroll
        for (int jj = 0; jj < 8; jj++) {
            const uint32_t co = (uint32_t)(e * 256 + 32 * jj);   // byte offset along y
            const int t0 = 2 * jj, t1 = 2 * jj + 1;
            #pragma unroll
            for (int nt = 0; nt < 8; nt += 2) {
                const uint32_t va = sb + SM_VT + nt * (8 * VSTR) + bVrow + co;
                uint32_t bh[4], bl[4];
                ldsm4(bh, va);
                mma16816(o[nt],     hi01[t0], hi23[t0], hi01[t1], hi23[t1], bh[0], bh[1]);
                mma16816(o[nt + 1], hi01[t0], hi23[t0], hi01[t1], hi23[t1], bh[2], bh[3]);
                mma16816(o[nt],     lo01[t0], lo23[t0], lo01[t1], lo23[t1], bh[0], bh[1]);
                mma16816(o[nt + 1], lo01[t0], lo23[t0], lo01[t1], lo23[t1], bh[2], bh[3]);
                ldsm4(bl, va + SM_VL);
                mma16816(o[nt],     hi01[t0], hi23[t0], hi01[t1], hi23[t1], bl[0], bl[1]);
                mma16816(o[nt + 1], hi01[t0], hi23[t0], hi01[t1], hi23[t1], bl[2], bl[3]);
            }
        }
    }

    // ================= 3-way reduce (via dead K area) + store out =====================
    float* scr0 = reinterpret_cast<float*>(smem + SM_K);              // e=0 partials
    float* scr1 = reinterpret_cast<float*>(smem + SM_K + 17408);      // e=2 partials
    if (e != 1) {
        float* dst = (e == 0) ? scr0 : scr1;
        #pragma unroll
        for (int nt = 0; nt < 8; nt++) {
            const int col = 8 * nt + 2 * (lane & 3);
            *reinterpret_cast<float2*>(dst + lr0 * OSTR + col) = make_float2(o[nt][0], o[nt][1]);
            *reinterpret_cast<float2*>(dst + (lr0 + 8) * OSTR + col) = make_float2(o[nt][2], o[nt][3]);
        }
    }
    __syncthreads();
    if (e == 1) {
        float* o0 = gOut + (size_t)(rowBase + lr0 * Hn) * Dn + 2 * (lane & 3);
        float* o1 = o0 + (size_t)8 * Hn * Dn;
        #pragma unroll
        for (int nt = 0; nt < 8; nt++) {
            const int col = 8 * nt + 2 * (lane & 3);
            float2 p0 = *reinterpret_cast<const float2*>(scr0 + lr0 * OSTR + col);
            float2 q0 = *reinterpret_cast<const float2*>(scr1 + lr0 * OSTR + col);
            float2 p1 = *reinterpret_cast<const float2*>(scr0 + (lr0 + 8) * OSTR + col);
            float2 q1 = *reinterpret_cast<const float2*>(scr1 + (lr0 + 8) * OSTR + col);
            *reinterpret_cast<float2*>(o0 + 8 * nt) =
                make_float2(o[nt][0] + p0.x + q0.x, o[nt][1] + p0.y + q0.y);
            *reinterpret_cast<float2*>(o1 + 8 * nt) =
                make_float2(o[nt][2] + p1.x + q1.x, o[nt][3] + p1.y + q1.y);
        }
    }
}

extern "C" void kernel_launch(void* const* d_in, const int* in_sizes, int n_in,
                              void* d_out, int out_size) {
    const float* Q = (const float*)d_in[0];
    const float* K = (const float*)d_in[1];
    const float* V = (const float*)d_in[2];
    float* out  = (float*)d_out;
    float* attn = out + (size_t)Bn * Sn * Hn * Dn;

    cudaFuncSetAttribute(swa_mma, cudaFuncAttributeMaxDynamicSharedMemorySize, SMEM_TOTAL);
    dim3 grid(Cn * 2, Hn, Bn);
    swa_mma<<<grid, NT, SMEM_TOTAL>>>(Q, K, V, out, attn);
}